// round 1
// baseline (speedup 1.0000x reference)
#include <cuda_runtime.h>

#define NN 100000
#define DF 16

// ---- device scratch (no allocations allowed) ----
__device__ float g_D[NN * DF];
__device__ float g_PrS[NN * DF];
__device__ float g_PcS[NN * DF];
__device__ int   g_rcnt[NN];
__device__ int   g_ccnt[NN];
__device__ float g_rowb[NN * DF];
__device__ float g_colb[NN * DF];
__device__ float g_diagb[NN * DF];
__device__ float g_pdsum[DF];
__device__ float g_pasum[DF];
__device__ float g_call[DF];   // all_scalar + bias[0]
__device__ float g_cdiag[DF];  // diag_scalar + bias[1]

__device__ __forceinline__ void red4(float* p, float4 v) {
    asm volatile("red.global.add.v4.f32 [%0], {%1,%2,%3,%4};"
                 :: "l"(p), "f"(v.x), "f"(v.y), "f"(v.z), "f"(v.w) : "memory");
}

// ---- K0: zero scratch ----
__global__ void k_zero() {
    int tid = blockIdx.x * blockDim.x + threadIdx.x;
    int stride = gridDim.x * blockDim.x;
    for (int t = tid; t < NN * DF; t += stride) {
        g_D[t] = 0.f; g_PrS[t] = 0.f; g_PcS[t] = 0.f;
    }
    for (int t = tid; t < NN; t += stride) { g_rcnt[t] = 0; g_ccnt[t] = 0; }
    if (tid < DF) { g_pdsum[tid] = 0.f; g_pasum[tid] = 0.f; }
}

// ---- K1: pooling pass (segment sums + counts + global sums) ----
__global__ void __launch_bounds__(256) k_pool(
    const float* __restrict__ vals, const int* __restrict__ row,
    const int* __restrict__ col, int nnz)
{
    __shared__ float s_pa[DF], s_pd[DF];
    if (threadIdx.x < DF) { s_pa[threadIdx.x] = 0.f; s_pd[threadIdx.x] = 0.f; }
    __syncthreads();

    float pa[DF], pd[DF];
#pragma unroll
    for (int k = 0; k < DF; k++) { pa[k] = 0.f; pd[k] = 0.f; }

    int tid = blockIdx.x * blockDim.x + threadIdx.x;
    int stride = gridDim.x * blockDim.x;
    for (int i = tid; i < nnz; i += stride) {
        int r = row[i], c = col[i];
        const float4* vp = (const float4*)(vals + (size_t)i * DF);
        float4 v0 = vp[0], v1 = vp[1], v2 = vp[2], v3 = vp[3];

        float* pr = &g_PrS[(size_t)r * DF];
        red4(pr + 0, v0); red4(pr + 4, v1); red4(pr + 8, v2); red4(pr + 12, v3);
        float* pc = &g_PcS[(size_t)c * DF];
        red4(pc + 0, v0); red4(pc + 4, v1); red4(pc + 8, v2); red4(pc + 12, v3);
        atomicAdd(&g_rcnt[r], 1);
        atomicAdd(&g_ccnt[c], 1);

        pa[0]  += v0.x; pa[1]  += v0.y; pa[2]  += v0.z; pa[3]  += v0.w;
        pa[4]  += v1.x; pa[5]  += v1.y; pa[6]  += v1.z; pa[7]  += v1.w;
        pa[8]  += v2.x; pa[9]  += v2.y; pa[10] += v2.z; pa[11] += v2.w;
        pa[12] += v3.x; pa[13] += v3.y; pa[14] += v3.z; pa[15] += v3.w;

        if (r == c) {
            float* dd = &g_D[(size_t)r * DF];
            red4(dd + 0, v0); red4(dd + 4, v1); red4(dd + 8, v2); red4(dd + 12, v3);
            pd[0]  += v0.x; pd[1]  += v0.y; pd[2]  += v0.z; pd[3]  += v0.w;
            pd[4]  += v1.x; pd[5]  += v1.y; pd[6]  += v1.z; pd[7]  += v1.w;
            pd[8]  += v2.x; pd[9]  += v2.y; pd[10] += v2.z; pd[11] += v2.w;
            pd[12] += v3.x; pd[13] += v3.y; pd[14] += v3.z; pd[15] += v3.w;
        }
    }

    // warp reduce, then block reduce via shared atomics, then 1 global atomic per block
#pragma unroll
    for (int k = 0; k < DF; k++) {
#pragma unroll
        for (int o = 16; o > 0; o >>= 1) {
            pa[k] += __shfl_down_sync(0xffffffffu, pa[k], o);
            pd[k] += __shfl_down_sync(0xffffffffu, pd[k], o);
        }
    }
    if ((threadIdx.x & 31) == 0) {
#pragma unroll
        for (int k = 0; k < DF; k++) {
            atomicAdd(&s_pa[k], pa[k]);
            atomicAdd(&s_pd[k], pd[k]);
        }
    }
    __syncthreads();
    if (threadIdx.x < DF) {
        atomicAdd(&g_pasum[threadIdx.x], s_pa[threadIdx.x]);
        atomicAdd(&g_pdsum[threadIdx.x], s_pd[threadIdx.x]);
    }
}

// ---- K2: scalar terms (pd, pa through W11..W14 + biases) ----
__global__ void k_scalars(const float* __restrict__ W, const float* __restrict__ bias,
                          int nnz) {
    int k = threadIdx.x;
    if (k >= DF) return;
    float inv_n = 1.f / (float)NN;
    float inv_e = 1.f / (float)nnz;
    float ds = 0.f, as = 0.f;
#pragma unroll
    for (int j = 0; j < DF; j++) {
        float pdj = g_pdsum[j] * inv_n;
        float paj = g_pasum[j] * inv_e;
        ds += pdj * W[11 * 256 + j * DF + k] + paj * W[13 * 256 + j * DF + k];
        as += pdj * W[12 * 256 + j * DF + k] + paj * W[14 * 256 + j * DF + k];
    }
    g_call[k]  = as + bias[k];
    g_cdiag[k] = ds + bias[DF + k];
}

// ---- K3: per-node broadcast vectors diag_b/row_b/col_b ----
__global__ void __launch_bounds__(256) k_node(const float* __restrict__ W) {
    __shared__ float sW[9 * DF * DF];  // W2..W10
    for (int t = threadIdx.x; t < 9 * DF * DF; t += blockDim.x)
        sW[t] = W[2 * DF * DF + t];
    __syncthreads();

    int n = blockIdx.x * blockDim.x + threadIdx.x;
    if (n >= NN) return;

    float rinv = 1.f / (float)max(g_rcnt[n], 1);
    float cinv = 1.f / (float)max(g_ccnt[n], 1);

    float dv[DF], prv[DF], pcv[DF];
    {
        const float4* dp  = (const float4*)&g_D[(size_t)n * DF];
        const float4* prp = (const float4*)&g_PrS[(size_t)n * DF];
        const float4* pcp = (const float4*)&g_PcS[(size_t)n * DF];
        *(float4*)&dv[0]  = dp[0];  *(float4*)&dv[4]  = dp[1];
        *(float4*)&dv[8]  = dp[2];  *(float4*)&dv[12] = dp[3];
        *(float4*)&prv[0] = prp[0]; *(float4*)&prv[4] = prp[1];
        *(float4*)&prv[8] = prp[2]; *(float4*)&prv[12] = prp[3];
        *(float4*)&pcv[0] = pcp[0]; *(float4*)&pcv[4] = pcp[1];
        *(float4*)&pcv[8] = pcp[2]; *(float4*)&pcv[12] = pcp[3];
    }
#pragma unroll
    for (int k = 0; k < DF; k++) { prv[k] *= rinv; pcv[k] *= cinv; }

    float db[DF], rb[DF], cb[DF];
#pragma unroll
    for (int k = 0; k < DF; k++) { db[k] = 0.f; rb[k] = 0.f; cb[k] = 0.f; }

#pragma unroll
    for (int j = 0; j < DF; j++) {
        float d = dv[j], pr = prv[j], pc = pcv[j];
#pragma unroll
        for (int k = 0; k < DF; k++) {
            db[k] += d * sW[(0 * DF + j) * DF + k] + pr * sW[(3 * DF + j) * DF + k]
                   + pc * sW[(6 * DF + j) * DF + k];
            rb[k] += d * sW[(1 * DF + j) * DF + k] + pr * sW[(4 * DF + j) * DF + k]
                   + pc * sW[(7 * DF + j) * DF + k];
            cb[k] += d * sW[(2 * DF + j) * DF + k] + pr * sW[(5 * DF + j) * DF + k]
                   + pc * sW[(8 * DF + j) * DF + k];
        }
    }

    float4* dbo = (float4*)&g_diagb[(size_t)n * DF];
    float4* rbo = (float4*)&g_rowb[(size_t)n * DF];
    float4* cbo = (float4*)&g_colb[(size_t)n * DF];
    dbo[0] = *(float4*)&db[0];  dbo[1] = *(float4*)&db[4];
    dbo[2] = *(float4*)&db[8];  dbo[3] = *(float4*)&db[12];
    rbo[0] = *(float4*)&rb[0];  rbo[1] = *(float4*)&rb[4];
    rbo[2] = *(float4*)&rb[8];  rbo[3] = *(float4*)&rb[12];
    cbo[0] = *(float4*)&cb[0];  cbo[1] = *(float4*)&cb[4];
    cbo[2] = *(float4*)&cb[8];  cbo[3] = *(float4*)&cb[12];
}

// ---- K4: main per-entry pass ----
__global__ void __launch_bounds__(256) k_main(
    const float* __restrict__ vals, const int* __restrict__ row,
    const int* __restrict__ col, const float* __restrict__ W,
    float* __restrict__ Y, int nnz)
{
    __shared__ float sW0[DF * DF];
    __shared__ float scall[DF], scdiag[DF];
    sW0[threadIdx.x] = W[threadIdx.x];  // blockDim == 256
    if (threadIdx.x < DF) {
        scall[threadIdx.x]  = g_call[threadIdx.x];
        scdiag[threadIdx.x] = g_cdiag[threadIdx.x];
    }
    __syncthreads();

    int i = blockIdx.x * blockDim.x + threadIdx.x;
    if (i >= nnz) return;

    int r = row[i], c = col[i];

    float v[DF];
    {
        const float4* vp = (const float4*)(vals + (size_t)i * DF);
        *(float4*)&v[0] = vp[0]; *(float4*)&v[4]  = vp[1];
        *(float4*)&v[8] = vp[2]; *(float4*)&v[12] = vp[3];
    }

    float y[DF];
    {
        const float4* rbp = (const float4*)&g_rowb[(size_t)r * DF];
        const float4* cbp = (const float4*)&g_colb[(size_t)c * DF];
        float rbv[DF], cbv[DF];
        *(float4*)&rbv[0] = rbp[0]; *(float4*)&rbv[4]  = rbp[1];
        *(float4*)&rbv[8] = rbp[2]; *(float4*)&rbv[12] = rbp[3];
        *(float4*)&cbv[0] = cbp[0]; *(float4*)&cbv[4]  = cbp[1];
        *(float4*)&cbv[8] = cbp[2]; *(float4*)&cbv[12] = cbp[3];
#pragma unroll
        for (int k = 0; k < DF; k++) y[k] = scall[k] + rbv[k] + cbv[k];
    }

    if (r == c) {
        const float4* dbp = (const float4*)&g_diagb[(size_t)r * DF];
        float dbv[DF];
        *(float4*)&dbv[0] = dbp[0]; *(float4*)&dbv[4]  = dbp[1];
        *(float4*)&dbv[8] = dbp[2]; *(float4*)&dbv[12] = dbp[3];
#pragma unroll
        for (int k = 0; k < DF; k++) y[k] += dbv[k] + scdiag[k];
    }

#pragma unroll
    for (int j = 0; j < DF; j++) {
        float vj = v[j];
#pragma unroll
        for (int k = 0; k < DF; k++) y[k] += vj * sW0[j * DF + k];
    }

    float4* yo = (float4*)(Y + (size_t)i * DF);
    yo[0] = *(float4*)&y[0]; yo[1] = *(float4*)&y[4];
    yo[2] = *(float4*)&y[8]; yo[3] = *(float4*)&y[12];
}

// ---- K5: transpose scatter-add ----
__global__ void __launch_bounds__(256) k_trans(
    const float* __restrict__ vals, const int* __restrict__ tin,
    const int* __restrict__ tout, const float* __restrict__ W,
    float* __restrict__ Y, int nnzt)
{
    __shared__ float sW1[DF * DF];
    sW1[threadIdx.x] = W[DF * DF + threadIdx.x];  // W[1], blockDim == 256
    __syncthreads();

    int t = blockIdx.x * blockDim.x + threadIdx.x;
    if (t >= nnzt) return;

    int ii = tin[t], io = tout[t];

    float v[DF];
    {
        const float4* vp = (const float4*)(vals + (size_t)ii * DF);
        *(float4*)&v[0] = vp[0]; *(float4*)&v[4]  = vp[1];
        *(float4*)&v[8] = vp[2]; *(float4*)&v[12] = vp[3];
    }

    float g[DF];
#pragma unroll
    for (int k = 0; k < DF; k++) g[k] = 0.f;
#pragma unroll
    for (int j = 0; j < DF; j++) {
        float vj = v[j];
#pragma unroll
        for (int k = 0; k < DF; k++) g[k] += vj * sW1[j * DF + k];
    }

    float* yp = Y + (size_t)io * DF;
    red4(yp + 0,  make_float4(g[0],  g[1],  g[2],  g[3]));
    red4(yp + 4,  make_float4(g[4],  g[5],  g[6],  g[7]));
    red4(yp + 8,  make_float4(g[8],  g[9],  g[10], g[11]));
    red4(yp + 12, make_float4(g[12], g[13], g[14], g[15]));
}

extern "C" void kernel_launch(void* const* d_in, const int* in_sizes, int n_in,
                              void* d_out, int out_size) {
    const float* vals = (const float*)d_in[0];
    const float* W    = (const float*)d_in[1];
    const float* bias = (const float*)d_in[2];
    const int* row    = (const int*)d_in[3];
    const int* col    = (const int*)d_in[4];
    const int* tin    = (const int*)d_in[5];
    const int* tout   = (const int*)d_in[6];
    float* Y = (float*)d_out;

    int nnz  = in_sizes[0] / DF;
    int nnzt = in_sizes[5];

    k_zero<<<2048, 256>>>();
    k_pool<<<2368, 256>>>(vals, row, col, nnz);
    k_scalars<<<1, 32>>>(W, bias, nnz);
    k_node<<<(NN + 255) / 256, 256>>>(W);
    k_main<<<(nnz + 255) / 256, 256>>>(vals, row, col, W, Y, nnz);
    k_trans<<<(nnzt + 255) / 256, 256>>>(vals, tin, tout, W, Y, nnzt);
}